// round 1
// baseline (speedup 1.0000x reference)
#include <cuda_runtime.h>
#include <cstdint>

// Problem dims (fixed for this problem instance)
#define ZD 16
#define YD 384
#define XD 384
#define ZP 18        // padded z (zero slice at 0 and 17)
#define YP 386       // padded y
#define XGW 96       // XD/4 code words per row
#define NWIN_I 17    // z-pairs
#define NWIN_Y 385   // window rows
#define NGX 25       // 16-window groups per row (last group: only window x=384)
#define TOTAL_B_THREADS (NWIN_I * NWIN_Y * NGX)          // 163625
#define B_BLOCKS ((TOTAL_B_THREADS + 255) / 256)          // 640
#define NP_WIN 148225.0                                   // 385*385

// Scratch (static __device__ — no allocation)
__device__ float    g_D[ZP * YP * XD];     // (s - l)^2, zero-padded in z/y
__device__ unsigned g_C[ZP * YP * XGW];    // packed code bytes: bit0=label, bit4=(s>0.5)
__device__ float    g_area_perm[256];      // area[spread(a)|spread(b)<<1] at index (a<<4)|b
__device__ float    g_part[3 * B_BLOCKS];  // block partials: [num | den | bce]

// ---------------------------------------------------------------------------
// kP: build permuted area LUT. index = (c_prev4 << 4) | c_new4, where nibble
// bit m corresponds to (dz*2+dy)=m; true byte bit = dz*4+dy*2+dx.
__global__ void kP(const float* __restrict__ area) {
    int i = threadIdx.x;           // 0..255
    int a = i >> 4, b = i & 15;    // a = dx=0 column code, b = dx=1 column code
    int byte = 0;
#pragma unroll
    for (int m = 0; m < 4; m++) {
        byte |= ((a >> m) & 1) << (2 * m);
        byte |= ((b >> m) & 1) << (2 * m + 1);
    }
    g_area_perm[i] = area[byte];
}

// ---------------------------------------------------------------------------
// kA: per-voxel precompute over the PADDED domain. 4 voxels per thread.
__global__ void kA(const float* __restrict__ pred, const int* __restrict__ lab) {
    int w = blockIdx.x * blockDim.x + threadIdx.x;
    const int W = ZP * YP * XGW;
    if (w >= W) return;
    int xg = w % XGW;
    int rem = w / XGW;
    int yp = rem % YP;
    int zp = rem / YP;

    float4 d4 = make_float4(0.f, 0.f, 0.f, 0.f);
    unsigned code = 0u;

    if (zp >= 1 && zp <= ZD && yp >= 1 && yp <= YD) {
        int z = zp - 1, y = yp - 1, x0 = xg * 4;
        const float4 p4 = *reinterpret_cast<const float4*>(pred + ((z * YD + y) * XD + x0));
        const int4   l4 = *reinterpret_cast<const int4*>(lab + ((z * YD + y) * XD + x0));

        float s0 = __fdividef(1.f, 1.f + __expf(-p4.x));
        float s1 = __fdividef(1.f, 1.f + __expf(-p4.y));
        float s2 = __fdividef(1.f, 1.f + __expf(-p4.z));
        float s3 = __fdividef(1.f, 1.f + __expf(-p4.w));

        float f0 = (float)l4.x, f1 = (float)l4.y, f2 = (float)l4.z, f3 = (float)l4.w;
        d4.x = (s0 - f0) * (s0 - f0);
        d4.y = (s1 - f1) * (s1 - f1);
        d4.z = (s2 - f2) * (s2 - f2);
        d4.w = (s3 - f3) * (s3 - f3);

        unsigned b0 = (unsigned)(l4.x & 1) | (s0 > 0.5f ? 0x10u : 0u);
        unsigned b1 = (unsigned)(l4.y & 1) | (s1 > 0.5f ? 0x10u : 0u);
        unsigned b2 = (unsigned)(l4.z & 1) | (s2 > 0.5f ? 0x10u : 0u);
        unsigned b3 = (unsigned)(l4.w & 1) | (s3 > 0.5f ? 0x10u : 0u);
        code = b0 | (b1 << 8) | (b2 << 16) | (b3 << 24);
    }

    int base = (zp * YP + yp) * XD + xg * 4;
    *reinterpret_cast<float4*>(g_D + base) = d4;
    g_C[(zp * YP + yp) * XGW + xg] = code;
}

// ---------------------------------------------------------------------------
// Rare-path BCE: byte==0 -> softplus(p), byte==255 -> softplus(-p), over valid corners.
__device__ __noinline__ float bce8(const float* __restrict__ pred, int i, int yw, int x, bool ones) {
    float s = 0.f;
#pragma unroll
    for (int dz = 0; dz < 2; dz++)
#pragma unroll
        for (int dy = 0; dy < 2; dy++)
#pragma unroll
            for (int dx = 0; dx < 2; dx++) {
                int z = i - 1 + dz, y = yw - 1 + dy, xv = x - 1 + dx;
                if (z >= 0 && z < ZD && y >= 0 && y < YD && xv >= 0 && xv < XD) {
                    float p = __ldg(&pred[(z * YD + y) * XD + xv]);
                    float u = ones ? -p : p;
                    s += fmaxf(u, 0.f) + __logf(1.f + __expf(-fabsf(u)));
                }
            }
    return s;
}

__device__ __forceinline__ unsigned wsel(uint4 u, int j) {
    return j == 0 ? u.x : (j == 1 ? u.y : (j == 2 ? u.z : u.w));
}

// ---------------------------------------------------------------------------
// kB: each thread sweeps 16 consecutive windows along x for a fixed (i, yw).
__global__ void kB(const float* __restrict__ pred) {
    __shared__ float a_sh[256];
    __shared__ float red[256];
    int tid = threadIdx.x;
    a_sh[tid] = g_area_perm[tid];
    __syncthreads();

    float accN = 0.f, accD = 0.f, accB = 0.f;
    int t = blockIdx.x * 256 + tid;
    if (t < TOTAL_B_THREADS) {
        int g = t % NGX;
        int rem = t / NGX;
        int yw = rem % NWIN_Y;
        int i = rem / NWIN_Y;
        int x0 = g * 16;

        // padded row bases: row r = dz*2+dy -> zp = i+dz, yp = yw+dy
        int rb0 = ((i + 0) * YP + (yw + 0)) * XD;
        int rb1 = ((i + 0) * YP + (yw + 1)) * XD;
        int rb2 = ((i + 1) * YP + (yw + 0)) * XD;
        int rb3 = ((i + 1) * YP + (yw + 1)) * XD;
        const unsigned char* C8 = reinterpret_cast<const unsigned char*>(g_C);

        // carry: column x0-1 (voxel coords); x0==0 -> zero-padded left column
        float colDp;
        unsigned ccp;
        if (x0 == 0) {
            colDp = 0.f;
            ccp = 0u;
        } else {
            int c = x0 - 1;
            colDp = (g_D[rb0 + c] + g_D[rb1 + c]) + (g_D[rb2 + c] + g_D[rb3 + c]);
            unsigned b0 = C8[rb0 + c], b1 = C8[rb1 + c], b2 = C8[rb2 + c], b3 = C8[rb3 + c];
            ccp = (b0 & 0x11u) | ((b1 & 0x11u) << 1) | ((b2 & 0x11u) << 2) | ((b3 & 0x11u) << 3);
        }

        // code words for columns x0..x0+15 (one uint4 = 16 bytes per row)
        uint4 u0, u1, u2, u3;
        if (x0 < XD) {
            u0 = *reinterpret_cast<const uint4*>(C8 + rb0 + x0);
            u1 = *reinterpret_cast<const uint4*>(C8 + rb1 + x0);
            u2 = *reinterpret_cast<const uint4*>(C8 + rb2 + x0);
            u3 = *reinterpret_cast<const uint4*>(C8 + rb3 + x0);
        } else {
            u0 = u1 = u2 = u3 = make_uint4(0, 0, 0, 0);
        }

#pragma unroll
        for (int j = 0; j < 4; j++) {
            int c0 = x0 + 4 * j;
            float4 d0, d1, d2, d3;
            unsigned w0, w1, w2, w3;
            if (c0 < XD) {
                d0 = *reinterpret_cast<const float4*>(g_D + rb0 + c0);
                d1 = *reinterpret_cast<const float4*>(g_D + rb1 + c0);
                d2 = *reinterpret_cast<const float4*>(g_D + rb2 + c0);
                d3 = *reinterpret_cast<const float4*>(g_D + rb3 + c0);
                w0 = wsel(u0, j); w1 = wsel(u1, j); w2 = wsel(u2, j); w3 = wsel(u3, j);
            } else {
                d0 = d1 = d2 = d3 = make_float4(0.f, 0.f, 0.f, 0.f);
                w0 = w1 = w2 = w3 = 0u;
            }
            // per-byte column codes: lab nibble in bits0-3, pred nibble in bits4-7
            const unsigned M = 0x11111111u;
            unsigned tt = (w0 & M) | ((w1 & M) << 1) | ((w2 & M) << 2) | ((w3 & M) << 3);

            float cd0 = (d0.x + d1.x) + (d2.x + d3.x);
            float cd1 = (d0.y + d1.y) + (d2.y + d3.y);
            float cd2 = (d0.z + d1.z) + (d2.z + d3.z);
            float cd3 = (d0.w + d1.w) + (d2.w + d3.w);
            float cd[4] = {cd0, cd1, cd2, cd3};

#pragma unroll
            for (int k = 0; k < 4; k++) {
                int x = c0 + k;                 // window index
                if (x <= 384) {                 // only false in last group
                    unsigned cc = __byte_perm(tt, 0u, 0x4440u | (unsigned)k);
                    float cdk = cd[k];
                    float q = colDp + cdk;
                    unsigned lidx = ((ccp << 4) & 0xF0u) | (cc & 0x0Fu);
                    unsigned pidx = (ccp & 0xF0u) | (cc >> 4);
                    float la = a_sh[lidx];
                    float pa = a_sh[pidx];
                    float pw = fmaf(q, -0.125f, 1.0f);
                    accN = fmaf(pw, la, accN);
                    accD += la + pa;
                    if (lidx == 0u || lidx == 255u) {
                        accB += bce8(pred, i, yw, x, lidx == 255u);
                    }
                    colDp = cdk;
                    ccp = cc;
                }
            }
        }
    }

    // deterministic block reductions
    red[tid] = accN;
    __syncthreads();
    for (int s = 128; s > 0; s >>= 1) { if (tid < s) red[tid] += red[tid + s]; __syncthreads(); }
    if (tid == 0) g_part[blockIdx.x] = red[0];
    __syncthreads();

    red[tid] = accD;
    __syncthreads();
    for (int s = 128; s > 0; s >>= 1) { if (tid < s) red[tid] += red[tid + s]; __syncthreads(); }
    if (tid == 0) g_part[B_BLOCKS + blockIdx.x] = red[0];
    __syncthreads();

    red[tid] = accB;
    __syncthreads();
    for (int s = 128; s > 0; s >>= 1) { if (tid < s) red[tid] += red[tid + s]; __syncthreads(); }
    if (tid == 0) g_part[2 * B_BLOCKS + blockIdx.x] = red[0];
}

// ---------------------------------------------------------------------------
// kF: final deterministic reduce (double) + scalar formula.
__global__ void kF(float* __restrict__ out) {
    __shared__ double rd[256];
    int tid = threadIdx.x;
    double sN = 0.0, sD = 0.0, sB = 0.0;
    for (int b = tid; b < B_BLOCKS; b += 256) {
        sN += (double)g_part[b];
        sD += (double)g_part[B_BLOCKS + b];
        sB += (double)g_part[2 * B_BLOCKS + b];
    }
    rd[tid] = sN; __syncthreads();
    for (int s = 128; s > 0; s >>= 1) { if (tid < s) rd[tid] += rd[tid + s]; __syncthreads(); }
    double tN = rd[0]; __syncthreads();
    rd[tid] = sD; __syncthreads();
    for (int s = 128; s > 0; s >>= 1) { if (tid < s) rd[tid] += rd[tid + s]; __syncthreads(); }
    double tD = rd[0]; __syncthreads();
    rd[tid] = sB; __syncthreads();
    for (int s = 128; s > 0; s >>= 1) { if (tid < s) rd[tid] += rd[tid + s]; __syncthreads(); }
    double tB = rd[0];

    if (tid == 0) {
        double dice = 1.0 - (2.0 * tN + 1e-3) / (tD + 1e-3);
        double vol = tB / (8.0 * NP_WIN);
        out[0] = (float)(dice + vol);
    }
}

// ---------------------------------------------------------------------------
extern "C" void kernel_launch(void* const* d_in, const int* in_sizes, int n_in,
                              void* d_out, int out_size) {
    const float* pred   = (const float*)d_in[0];
    const int*   labels = (const int*)d_in[1];
    const float* area   = (const float*)d_in[2];

    kP<<<1, 256>>>(area);
    const int W = ZP * YP * XGW;
    kA<<<(W + 255) / 256, 256>>>(pred, labels);
    kB<<<B_BLOCKS, 256>>>(pred);
    kF<<<1, 256>>>((float*)d_out);
}